// round 15
// baseline (speedup 1.0000x reference)
#include <cuda_runtime.h>
#include <cuda_bf16.h>
#include <math.h>
#include <float.h>
#include <stdint.h>

#define BB 8
#define TT 4096
#define HH 128
#define NBLK 6
#define KK 20
#define BT (BB*TT)   // 32768
#define SX 132       // f32 tile stride (final_kernel only)
#define ATILE 8192   // A image words per tile: 8 chunks x 64 rows x 16 words

typedef unsigned long long u64;

// packed f32x2 helpers (scalar kernels)
#define FMA2(d, a, b, c) \
    asm("fma.rn.f32x2 %0, %1, %2, %3;" : "=l"(d) : "l"(a), "l"(b), "l"(c))
#define BCAST2(d, s) \
    asm("mov.b64 %0, {%1, %1};" : "=l"(d) : "r"(s))

// bf16 mma (sm_80+ PTX, valid at target sm_103)
#define MMA_BF16(d, a, b) \
    asm volatile("mma.sync.aligned.m16n8k16.row.col.f32.bf16.bf16.f32 " \
        "{%0,%1,%2,%3}, {%4,%5,%6,%7}, {%8,%9}, {%0,%1,%2,%3};" \
        : "+f"((d)[0]), "+f"((d)[1]), "+f"((d)[2]), "+f"((d)[3]) \
        : "r"((a)[0]), "r"((a)[1]), "r"((a)[2]), "r"((a)[3]), \
          "r"((b)[0]), "r"((b)[1]))

// pack two f32 into bf16x2: low 16 bits <- vlo, high <- vhi
__device__ __forceinline__ uint32_t pack_bf16x2(float vlo, float vhi) {
    uint32_t r;
    asm("cvt.rn.bf16x2.f32 %0, %1, %2;" : "=r"(r) : "f"(vhi), "f"(vlo));
    return r;
}

// split f32 pair -> (hi word, lo word)
__device__ __forceinline__ void split2(float x, float y, uint32_t& wh, uint32_t& wl) {
    wh = pack_bf16x2(x, y);
    float h0 = __uint_as_float(wh << 16);
    float h1 = __uint_as_float(wh & 0xffff0000u);
    wl = pack_bf16x2(x - h0, y - h1);
}

// ---------------- scratch (device globals; no allocation) ----------------
__device__ float g_net[BT * HH];   // 16 MB
__device__ float g_att[BT * HH];   // 16 MB
__device__ int   g_idx[BT * KK];
__device__ float g_dis[BT * KK];
// prepped weights: per block 48 K16-chunks x 2048 quad-packed words
__device__ float g_bprep[NBLK * 48 * 2048];   // 2.4 MB

// ======================= KNN (2 threads/query, shared tile) =============
// 256 threads, 128 queries/block. Thread (q, half) scans the half-tile
// sp[half*512 .. half*512+512) of every 1024-candidate window. Tiles are
// loaded once by all 256 threads (no duplicated traffic). Exact merge of
// the two sorted top-20 lists, then fused positional encoding.
__global__ __launch_bounds__(256) void knn_kernel(const float* __restrict__ p,
                                                  const float* __restrict__ W_pos,
                                                  const float* __restrict__ b_pos)
{
    extern __shared__ char ksm[];
    float4* sp = (float4*)ksm;                       // [1024] window tile
    float*  ld = (float*)(ksm + 16384);              // [256][20]
    int*    li = (int*)(ksm + 16384 + 256*KK*4);     // [256][20]

    const int b    = blockIdx.y;
    const int tid  = threadIdx.x;
    const int q    = tid & 127;
    const int half = tid >> 7;
    const int tt   = blockIdx.x * 128 + q;
    const float* pb = p + (size_t)b * TT * 3;

    const float qx = pb[tt*3 + 0];
    const float qy = pb[tt*3 + 1];
    const float qz = pb[tt*3 + 2];
    const float sqq = (qx*qx + qy*qy) + qz*qz;

    float bd[KK];
    int   bi[KK];
#pragma unroll
    for (int k = 0; k < KK; ++k) { bd[k] = FLT_MAX; bi[k] = 0; }

    const int base = half * 512;

    for (int s0 = 0; s0 < TT; s0 += 1024) {
        __syncthreads();
        for (int l = tid; l < 1024; l += 256) {
            const float* qq = pb + (size_t)(s0 + l) * 3;
            float x = qq[0], y = qq[1], z = qq[2];
            sp[l] = make_float4(x, y, z, (x*x + y*y) + z*z);
        }
        __syncthreads();
#pragma unroll 4
        for (int l = 0; l < 512; ++l) {
            float4 v = sp[base + l];
            float dot = qx*v.x + qy*v.y + qz*v.z;
            float d2  = sqq + v.w - 2.0f * dot;
            if (d2 < bd[KK-1]) {
                bd[KK-1] = d2; bi[KK-1] = s0 + base + l;
#pragma unroll
                for (int q2 = KK-1; q2 > 0; --q2) {
                    if (bd[q2] < bd[q2-1]) {
                        float td = bd[q2]; bd[q2] = bd[q2-1]; bd[q2-1] = td;
                        int   ti = bi[q2]; bi[q2] = bi[q2-1]; bi[q2-1] = ti;
                    }
                }
            }
        }
    }

    __syncthreads();
#pragma unroll
    for (int k = 0; k < KK; ++k) {
        ld[tid * KK + k] = bd[k];
        li[tid * KK + k] = bi[k];
    }
    __syncthreads();

    if (tid < 128) {
        const float* la = ld + tid * KK;
        const int*   ia = li + tid * KK;
        const float* lb = ld + (tid + 128) * KK;
        const int*   ib = li + (tid + 128) * KK;
        int pa = 0, pbi = 0;
        const size_t o = ((size_t)b * TT + tt) * KK;
#pragma unroll
        for (int k = 0; k < KK; ++k) {
            float da = la[pa], db = lb[pbi];
            bool takeA = da <= db;
            float d = takeA ? da : db;
            int   ix = takeA ? ia[pa] : ib[pbi];
            pa += takeA; pbi += !takeA;
            g_idx[o + k] = ix;
            g_dis[o + k] = sqrtf(fmaxf(d, 1e-12f));
        }

        // ---- fused positional encoding
        float* dst = g_net + ((size_t)b * TT + tt) * HH;
#pragma unroll 4
        for (int h4 = 0; h4 < HH; h4 += 4) {
            float4 w0 = *(const float4*)(W_pos + h4);
            float4 w1 = *(const float4*)(W_pos + HH + h4);
            float4 w2 = *(const float4*)(W_pos + 2*HH + h4);
            float4 bb = *(const float4*)(b_pos + h4);
            float4 ov;
            ov.x = fmaf(qz, w2.x, fmaf(qy, w1.x, fmaf(qx, w0.x, bb.x)));
            ov.y = fmaf(qz, w2.y, fmaf(qy, w1.y, fmaf(qx, w0.y, bb.y)));
            ov.z = fmaf(qz, w2.z, fmaf(qy, w1.z, fmaf(qx, w0.z, bb.z)));
            ov.w = fmaf(qz, w2.w, fmaf(qy, w1.w, fmaf(qx, w0.w, bb.w)));
            *(float4*)(dst + h4) = ov;
        }
    }
}

// ======================= attention (gather + softmax) ===================
__global__ __launch_bounds__(256) void attn_kernel(const float* __restrict__ p,
                                                   const float* __restrict__ wc,
                                                   const float* __restrict__ bc)
{
    const int warp = threadIdx.x >> 5;
    const int lane = threadIdx.x & 31;
    const int t  = blockIdx.x * 8 + warp;
    const int b  = t >> 12;
    const int tt = t & (TT - 1);
    const float* pb = p + (size_t)b * TT * 3;

    const float q0 = pb[tt*3+0], q1 = pb[tt*3+1], q2 = pb[tt*3+2];
    const float w0 = wc[0], w1 = wc[1], w2 = wc[2], w3 = wc[3];
    const float w4 = wc[4], w5 = wc[5], w6 = wc[6], bcv = bc[0];

    float s = -FLT_MAX;
    int   j = 0;
    if (lane < KK) {
        size_t o = (size_t)t * KK + lane;
        j = g_idx[o];
        float d = g_dis[o];
        const float* px = pb + (size_t)j * 3;
        s = bcv;
        s = fmaf(w0, d,     s);
        s = fmaf(w1, px[0], s);
        s = fmaf(w2, px[1], s);
        s = fmaf(w3, px[2], s);
        s = fmaf(w4, q0,    s);
        s = fmaf(w5, q1,    s);
        s = fmaf(w6, q2,    s);
    }
    float m = s;
#pragma unroll
    for (int off = 16; off; off >>= 1)
        m = fmaxf(m, __shfl_xor_sync(0xffffffffu, m, off));
    float e = (lane < KK) ? expf(s - m) : 0.0f;
    float sum = e;
#pragma unroll
    for (int off = 16; off; off >>= 1)
        sum += __shfl_xor_sync(0xffffffffu, sum, off);
    const float inv = 1.0f / sum;

    float4 acc = make_float4(0.f, 0.f, 0.f, 0.f);
    const float* nb = g_net + (size_t)b * TT * HH;
#pragma unroll
    for (int k = 0; k < KK; ++k) {
        float wk = __shfl_sync(0xffffffffu, e, k) * inv;
        int   jk = __shfl_sync(0xffffffffu, j, k);
        float4 v = *(const float4*)(nb + (size_t)jk * HH + lane * 4);
        acc.x = fmaf(wk, v.x, acc.x);
        acc.y = fmaf(wk, v.y, acc.y);
        acc.z = fmaf(wk, v.z, acc.z);
        acc.w = fmaf(wk, v.w, acc.w);
    }
    *(float4*)(g_att + (size_t)t * HH + lane * 4) = acc;
}

// ======================= weight prep (quad-packed bf16) ==================
__global__ __launch_bounds__(256) void prep_weights(
    const float* __restrict__ Wo, const float* __restrict__ W0,
    const float* __restrict__ W1, const float* __restrict__ Ws)
{
    const int blk = blockIdx.y;
    const int slot = blockIdx.x;
    const float* W; int ck;
    if (slot < 8)       { W = Wo + (size_t)blk*128*128; ck = slot; }
    else if (slot < 24) { W = W0 + (size_t)blk*256*128; ck = slot-8; }
    else if (slot < 32) { W = W1 + (size_t)blk*128*128; ck = slot-24; }
    else                { W = Ws + (size_t)blk*256*128; ck = slot-32; }
    float* img = g_bprep + ((size_t)blk*48 + slot)*2048;

    for (int it = threadIdx.x; it < 512; it += 256) {
        int n = it >> 2, t = it & 3;
        int k0 = ck*16 + 2*t;
        float a0 = W[(size_t)k0*128 + n];
        float a1 = W[(size_t)(k0+1)*128 + n];
        float a2 = W[(size_t)(k0+8)*128 + n];
        float a3 = W[(size_t)(k0+9)*128 + n];
        uint32_t h0, l0, h1, l1;
        split2(a0, a1, h0, l0);
        split2(a2, a3, h1, l1);
        uint4 q = make_uint4(h0, h1, l0, l1);
        *(uint4*)(img + n*16 + t*4) = q;
    }
}

// ======================= tensor-core resnet (64-token CTA, 2 CTAs/SM) ====
__device__ __forceinline__ void init_acc(float acc[2][4][4],
                                         const float* __restrict__ bias,
                                         int nb, int tig)
{
#pragma unroll
    for (int j = 0; j < 4; ++j) {
        int col0 = nb + j*8 + 2*tig;
        float b0v = __ldg(bias + col0);
        float b1v = __ldg(bias + col0 + 1);
#pragma unroll
        for (int mt = 0; mt < 2; ++mt) {
            acc[mt][j][0] = b0v; acc[mt][j][1] = b1v;
            acc[mt][j][2] = b0v; acc[mt][j][3] = b1v;
        }
    }
}

// zero both hi/lo halves of the split where the hi half is negative
__device__ __forceinline__ void relu_mask(uint32_t& ah, uint32_t& al)
{
    uint32_t t = ah & 0x80008000u;
    uint32_t m = t - (t >> 15);
    uint32_t full = t | m;
    ah &= ~full;
    al &= ~full;
}

template<bool RELU>
__device__ __forceinline__ void gemm_tc(
    const uint32_t* At, const float* __restrict__ prep, int nchunks,
    float acc[2][4][4], uint32_t* Bs, int tid, int rb, int nb)
{
    const int lane = tid & 31;
    const int gid = lane >> 2, tig = lane & 3;

    // stage chunk 0
    __syncthreads();
    {
        const float4* s = (const float4*)prep;
        *(float4*)(Bs + tid*4)        = s[tid];
        *(float4*)(Bs + 1024 + tid*4) = s[tid + 256];
    }
    __syncthreads();

    for (int c = 0; c < nchunks; ++c) {
        const uint32_t* buf = Bs + (c & 1) * 2048;
        float4 pre0, pre1;
        if (c + 1 < nchunks) {
            const float4* s = (const float4*)(prep + (size_t)(c+1) * 2048);
            pre0 = s[tid];
            pre1 = s[tid + 256];
        }

        uint32_t Ah[2][4], Al[2][4];
#pragma unroll
        for (int mt = 0; mt < 2; ++mt) {
            const uint32_t* ap = At + (size_t)c*1024 + (rb + mt*16 + gid)*16 + tig*4;
            uint4 qa = *(const uint4*)ap;
            uint4 qb = *(const uint4*)(ap + 128);   // row + 8
            Ah[mt][0] = qa.x; Ah[mt][2] = qa.y; Al[mt][0] = qa.z; Al[mt][2] = qa.w;
            Ah[mt][1] = qb.x; Ah[mt][3] = qb.y; Al[mt][1] = qb.z; Al[mt][3] = qb.w;
            if (RELU) {
#pragma unroll
                for (int i = 0; i < 4; ++i)
                    relu_mask(Ah[mt][i], Al[mt][i]);
            }
        }
#pragma unroll
        for (int j = 0; j < 4; ++j) {
            const int n = nb + j*8 + gid;
            uint4 q = *(const uint4*)(buf + n*16 + tig*4);
            uint32_t bh[2] = { q.x, q.y };
            uint32_t bl[2] = { q.z, q.w };
            // pass-major issue: dependent MMAs on the same acc are 2 apart
            MMA_BF16(acc[0][j], Ah[0], bh);
            MMA_BF16(acc[1][j], Ah[1], bh);
            MMA_BF16(acc[0][j], Al[0], bh);
            MMA_BF16(acc[1][j], Al[1], bh);
            MMA_BF16(acc[0][j], Ah[0], bl);
            MMA_BF16(acc[1][j], Ah[1], bl);
        }
        if (c + 1 < nchunks) {
            uint32_t* nbuf = Bs + ((c+1) & 1) * 2048;
            *(float4*)(nbuf + tid*4)        = pre0;
            *(float4*)(nbuf + 1024 + tid*4) = pre1;
        }
        __syncthreads();
    }
}

// store accumulators into a quad-packed bf16 tile (optionally relu'd first)
template<bool RELU>
__device__ __forceinline__ void store_acc_tile(float acc[2][4][4], uint32_t* tile,
                                               int rb, int nb, int lane)
{
    const int gid = lane >> 2, tig = lane & 3;
#pragma unroll
    for (int mt = 0; mt < 2; ++mt) {
        const int rg = rb + mt*16 + gid;
#pragma unroll
        for (int j = 0; j < 4; ++j) {
            const int kp = (nb >> 1) + j*4 + tig;     // global kpair 0..63
            const int c = kp >> 3, tq = kp & 7;
            const int base = c*1024 + (tq & 3)*4 + (tq >> 2);
            float v0 = acc[mt][j][0], v1 = acc[mt][j][1];
            float v2 = acc[mt][j][2], v3 = acc[mt][j][3];
            if (RELU) {
                v0 = fmaxf(v0, 0.f); v1 = fmaxf(v1, 0.f);
                v2 = fmaxf(v2, 0.f); v3 = fmaxf(v3, 0.f);
            }
            uint32_t wh, wl;
            split2(v0, v1, wh, wl);
            tile[base + rg*16]     = wh;
            tile[base + rg*16 + 2] = wl;
            split2(v2, v3, wh, wl);
            tile[base + (rg+8)*16]     = wh;
            tile[base + (rg+8)*16 + 2] = wl;
        }
    }
}

__global__ __launch_bounds__(256, 2) void resnet_tc(
    int blk,
    const float* __restrict__ b0, const float* __restrict__ b1,
    const float* __restrict__ bo, int add_res)
{
    extern __shared__ uint32_t sm[];
    uint32_t* xs  = sm;               // [ATILE]
    uint32_t* as_ = sm + ATILE;
    uint32_t* hs  = sm + 2*ATILE;
    uint32_t* Bs  = sm + 3*ATILE;     // 2 x 2048 double buffer

    const int tid = threadIdx.x;
    const int wid = tid >> 5, lane = tid & 31;
    const int rb = (wid & 1) * 32;          // 2 row groups of 32
    const int nb = (wid >> 1) * 32;         // 4 col groups of 32
    const int gid = lane >> 2, tig = lane & 3;
    const size_t t0 = (size_t)blockIdx.x * 64;
    const float* prep = g_bprep + (size_t)blk * 48 * 2048;

    // build xs (net) and hs (att) quad-packed images (64 rows)
    for (int it = tid; it < 2048; it += 256) {
        int r = it >> 5, rem = it & 31;
        int c = rem >> 2, t = rem & 3;
        int e0 = 16*c + 2*t;
        const float* src = g_net + (t0 + r) * HH;
        float2 p0 = *(const float2*)(src + e0);
        float2 p1 = *(const float2*)(src + e0 + 8);
        uint32_t h0, l0, h1, l1;
        split2(p0.x, p0.y, h0, l0);
        split2(p1.x, p1.y, h1, l1);
        *(uint4*)(xs + c*1024 + r*16 + t*4) = make_uint4(h0, h1, l0, l1);
        src = g_att + (t0 + r) * HH;
        p0 = *(const float2*)(src + e0);
        p1 = *(const float2*)(src + e0 + 8);
        split2(p0.x, p0.y, h0, l0);
        split2(p1.x, p1.y, h1, l1);
        *(uint4*)(hs + c*1024 + r*16 + t*4) = make_uint4(h0, h1, l0, l1);
    }

    float acc[2][4][4];

    // ---- GEMM1: a1 = att @ Wo^T + bo -> as_ (plain split)
    init_acc(acc, bo, nb, tig);
    gemm_tc<false>(hs, prep + 0*2048, 8, acc, Bs, tid, rb, nb);
    store_acc_tile<false>(acc, as_, rb, nb, lane);

    // ---- GEMM2: h = relu(relu([x|a1]) @ W0 + b0) -> hs (relu'd split)
    init_acc(acc, b0, nb, tig);
    gemm_tc<true>(xs,  prep + 8*2048,  8, acc, Bs, tid, rb, nb);
    gemm_tc<true>(as_, prep + 16*2048, 8, acc, Bs, tid, rb, nb);
    __syncthreads();
    store_acc_tile<true>(acc, hs, rb, nb, lane);

    // ---- GEMM3+4: out = h @ W1^T + b1 + [x|a1] @ Ws^T [+ residual]
    init_acc(acc, b1, nb, tig);
    gemm_tc<false>(hs,  prep + 24*2048, 8, acc, Bs, tid, rb, nb);
    gemm_tc<false>(xs,  prep + 32*2048, 8, acc, Bs, tid, rb, nb);
    gemm_tc<false>(as_, prep + 40*2048, 8, acc, Bs, tid, rb, nb);

#pragma unroll
    for (int mt = 0; mt < 2; ++mt) {
        const int rg = rb + mt*16 + gid;
#pragma unroll
        for (int j = 0; j < 4; ++j) {
            const int col0 = nb + j*8 + 2*tig;
            float v0 = acc[mt][j][0], v1 = acc[mt][j][1];
            float v2 = acc[mt][j][2], v3 = acc[mt][j][3];
            float* d0 = g_net + (t0 + rg) * HH + col0;
            float* d1 = g_net + (t0 + rg + 8) * HH + col0;
            if (add_res) {
                float2 r0 = *(const float2*)d0;
                float2 r1 = *(const float2*)d1;
                v0 += r0.x; v1 += r0.y; v2 += r1.x; v3 += r1.y;
            }
            *(float2*)d0 = make_float2(v0, v1);
            *(float2*)d1 = make_float2(v2, v3);
        }
    }
}

// ======================= final projection (scalar, FFMA2) ===============
__device__ __forceinline__ void init_bias_f(u64 acc[8][4], const float* __restrict__ bias, int nb)
{
    ulonglong2 q0 = *(const ulonglong2*)(bias + nb);
    ulonglong2 q1 = *(const ulonglong2*)(bias + nb + 4);
#pragma unroll
    for (int r = 0; r < 8; ++r) {
        acc[r][0] = q0.x; acc[r][1] = q0.y; acc[r][2] = q1.x; acc[r][3] = q1.y;
    }
}

__global__ __launch_bounds__(256) void final_kernel(const float* __restrict__ W_c,
                                                    const float* __restrict__ b_c,
                                                    float* __restrict__ out)
{
    extern __shared__ float smf[];
    float* xs = smf;             // [128][SX]
    float* ws = smf + 128 * SX;  // [32][128]

    const int tid = threadIdx.x;
    const int tx = tid & 15;
    const int ty = tid >> 4;
    const int nb = tx * 8;
    const int rb = ty * 8;
    const size_t t0 = (size_t)blockIdx.x * 128;

    for (int q = tid; q < 128 * 32; q += 256) {
        int r = q >> 5, c = (q & 31) << 2;
        *(float4*)(xs + r * SX + c) = *(const float4*)(g_net + (t0 + r) * HH + c);
    }

    u64 acc[8][4];
    init_bias_f(acc, b_c, nb);

    for (int kt = 0; kt < 128; kt += 32) {
        __syncthreads();
        for (int q = tid; q < 1024; q += 256) {
            int kk = q >> 5, c = (q & 31) << 2;
            *(float4*)(ws + kk * 128 + c) = *(const float4*)(W_c + (size_t)(kt + kk) * 128 + c);
        }
        __syncthreads();
#pragma unroll 1
        for (int k4 = 0; k4 < 8; ++k4) {
            float4 a4[8];
#pragma unroll
            for (int r = 0; r < 8; ++r)
                a4[r] = *(const float4*)(xs + (rb + r) * SX + kt + k4 * 4);
#pragma unroll
            for (int j = 0; j < 4; ++j) {
                int kk = k4 * 4 + j;
                ulonglong2 b0v = *(const ulonglong2*)(ws + kk * 128 + nb);
                ulonglong2 b1v = *(const ulonglong2*)(ws + kk * 128 + nb + 4);
#pragma unroll
                for (int r = 0; r < 8; ++r) {
                    float a = ((const float*)&a4[r])[j];
                    u64 aa; BCAST2(aa, __float_as_uint(a));
                    FMA2(acc[r][0], aa, b0v.x, acc[r][0]);
                    FMA2(acc[r][1], aa, b0v.y, acc[r][1]);
                    FMA2(acc[r][2], aa, b1v.x, acc[r][2]);
                    FMA2(acc[r][3], aa, b1v.y, acc[r][3]);
                }
            }
        }
    }
#pragma unroll
    for (int r = 0; r < 8; ++r) {
        *(ulonglong2*)(out + (t0 + rb + r) * HH + nb)     = make_ulonglong2(acc[r][0], acc[r][1]);
        *(ulonglong2*)(out + (t0 + rb + r) * HH + nb + 4) = make_ulonglong2(acc[r][2], acc[r][3]);
    }
}

// ======================= launch =========================================
extern "C" void kernel_launch(void* const* d_in, const int* in_sizes, int n_in,
                              void* d_out, int out_size)
{
    const float* p      = (const float*)d_in[0];
    const float* W_pos  = (const float*)d_in[1];
    const float* b_pos  = (const float*)d_in[2];
    const float* blk_W0 = (const float*)d_in[3];
    const float* blk_b0 = (const float*)d_in[4];
    const float* blk_W1 = (const float*)d_in[5];
    const float* blk_b1 = (const float*)d_in[6];
    const float* blk_Ws = (const float*)d_in[7];
    const float* att_Wc = (const float*)d_in[8];
    const float* att_bc = (const float*)d_in[9];
    const float* att_Wo = (const float*)d_in[10];
    const float* att_bo = (const float*)d_in[11];
    const float* W_c    = (const float*)d_in[12];
    const float* b_c    = (const float*)d_in[13];
    float* out = (float*)d_out;

    const int RES_SMEM = (3 * ATILE + 2 * 2048) * 4;   // 114,688 B -> 2 CTAs/SM
    const int FIN_SMEM = (128 * SX + 32 * 128) * 4;    //  83,968 B
    const int KNN_SMEM = 16384 + 256 * KK * 8;         //  57,344 B
    cudaFuncSetAttribute(resnet_tc,   cudaFuncAttributeMaxDynamicSharedMemorySize, RES_SMEM);
    cudaFuncSetAttribute(final_kernel, cudaFuncAttributeMaxDynamicSharedMemorySize, FIN_SMEM);
    cudaFuncSetAttribute(knn_kernel,  cudaFuncAttributeMaxDynamicSharedMemorySize, KNN_SMEM);

    // launch order: raw2=prep, raw3=knn(+pos), raw4=attn0, raw5=resnet0
    prep_weights<<<dim3(48, NBLK), 256>>>(att_Wo, blk_W0, blk_W1, blk_Ws);
    knn_kernel<<<dim3(TT / 128, BB), 256, KNN_SMEM>>>(p, W_pos, b_pos);

    for (int i = 0; i < NBLK; ++i) {
        attn_kernel<<<BT / 8, 256>>>(p, att_Wc + (size_t)i * 7, att_bc + i);
        resnet_tc<<<BT / 64, 256, RES_SMEM>>>(
            i, blk_b0 + (size_t)i * 128, blk_b1 + (size_t)i * 128,
            att_bo + (size_t)i * 128, i > 0 ? 1 : 0);
    }
    final_kernel<<<BT / 128, 256, FIN_SMEM>>>(W_c, b_c, out);
}

// round 16
// speedup vs baseline: 1.0751x; 1.0751x over previous
#include <cuda_runtime.h>
#include <cuda_bf16.h>
#include <math.h>
#include <float.h>
#include <stdint.h>

#define BB 8
#define TT 4096
#define HH 128
#define NBLK 6
#define KK 20
#define BT (BB*TT)   // 32768
#define SX 132       // f32 tile stride (final_kernel only)
#define ATILE 8192   // A image words per tile: 8 chunks x 64 rows x 16 words

typedef unsigned long long u64;

// packed f32x2 helpers (scalar kernels)
#define FMA2(d, a, b, c) \
    asm("fma.rn.f32x2 %0, %1, %2, %3;" : "=l"(d) : "l"(a), "l"(b), "l"(c))
#define BCAST2(d, s) \
    asm("mov.b64 %0, {%1, %1};" : "=l"(d) : "r"(s))

// bf16 mma (sm_80+ PTX, valid at target sm_103)
#define MMA_BF16(d, a, b) \
    asm volatile("mma.sync.aligned.m16n8k16.row.col.f32.bf16.bf16.f32 " \
        "{%0,%1,%2,%3}, {%4,%5,%6,%7}, {%8,%9}, {%0,%1,%2,%3};" \
        : "+f"((d)[0]), "+f"((d)[1]), "+f"((d)[2]), "+f"((d)[3]) \
        : "r"((a)[0]), "r"((a)[1]), "r"((a)[2]), "r"((a)[3]), \
          "r"((b)[0]), "r"((b)[1]))

// pack two f32 into bf16x2: low 16 bits <- vlo, high <- vhi
__device__ __forceinline__ uint32_t pack_bf16x2(float vlo, float vhi) {
    uint32_t r;
    asm("cvt.rn.bf16x2.f32 %0, %1, %2;" : "=r"(r) : "f"(vhi), "f"(vlo));
    return r;
}

// split f32 pair -> (hi word, lo word)
__device__ __forceinline__ void split2(float x, float y, uint32_t& wh, uint32_t& wl) {
    wh = pack_bf16x2(x, y);
    float h0 = __uint_as_float(wh << 16);
    float h1 = __uint_as_float(wh & 0xffff0000u);
    wl = pack_bf16x2(x - h0, y - h1);
}

// ---------------- scratch (device globals; no allocation) ----------------
__device__ float g_net[BT * HH];   // 16 MB
__device__ float g_att[BT * HH];   // 16 MB
__device__ int   g_idx[BT * KK];
__device__ float g_dis[BT * KK];
// prepped weights: per block 48 K16-chunks x 2048 quad-packed words
__device__ float g_bprep[NBLK * 48 * 2048];   // 2.4 MB

// ======================= KNN (smem top-20, replace-max) =================
// 128 threads/block, 1 query/thread. Top-20 kept UNSORTED in shared memory
// (per-thread column, conflict-free); register-cached (max, argmax) makes
// the threshold test cheap and the insert path ~85 slots instead of ~140.
// Output order is arbitrary (softmax over K is permutation-invariant).
__global__ __launch_bounds__(128) void knn_kernel(const float* __restrict__ p,
                                                  const float* __restrict__ W_pos,
                                                  const float* __restrict__ b_pos)
{
    __shared__ float4 sp[1024];       // candidate window tile
    __shared__ float  sd[KK * 128];   // distances, sd[k*128+tid]
    __shared__ int    si[KK * 128];   // indices

    const int b   = blockIdx.y;
    const int tid = threadIdx.x;
    const int tt  = blockIdx.x * 128 + tid;
    const float* pb = p + (size_t)b * TT * 3;

    const float qx = pb[tt*3 + 0];
    const float qy = pb[tt*3 + 1];
    const float qz = pb[tt*3 + 2];
    const float sqq = (qx*qx + qy*qy) + qz*qz;

#pragma unroll
    for (int k = 0; k < KK; ++k) sd[k*128 + tid] = FLT_MAX;
    float maxv = FLT_MAX;
    int   maxslot = 0;

    for (int s0 = 0; s0 < TT; s0 += 1024) {
        __syncthreads();
        for (int l = tid; l < 1024; l += 128) {
            const float* q = pb + (size_t)(s0 + l) * 3;
            float x = q[0], y = q[1], z = q[2];
            sp[l] = make_float4(x, y, z, (x*x + y*y) + z*z);
        }
        __syncthreads();
#pragma unroll 4
        for (int l = 0; l < 1024; ++l) {
            float4 v = sp[l];
            float dot = qx*v.x + qy*v.y + qz*v.z;
            float d2  = sqq + v.w - 2.0f * dot;
            if (d2 < maxv) {
                sd[maxslot*128 + tid] = d2;
                si[maxslot*128 + tid] = s0 + l;
                float mv = sd[tid];
                int   m  = 0;
#pragma unroll
                for (int k = 1; k < KK; ++k) {
                    float w = sd[k*128 + tid];
                    if (w > mv) { mv = w; m = k; }
                }
                maxv = mv;
                maxslot = m;
            }
        }
    }

    const size_t o = ((size_t)b * TT + tt) * KK;
#pragma unroll
    for (int k = 0; k < KK; ++k) {
        g_idx[o + k] = si[k*128 + tid];
        g_dis[o + k] = sqrtf(fmaxf(sd[k*128 + tid], 1e-12f));
    }

    // ---- fused positional encoding
    float* dst = g_net + ((size_t)b * TT + tt) * HH;
#pragma unroll 4
    for (int h4 = 0; h4 < HH; h4 += 4) {
        float4 w0 = *(const float4*)(W_pos + h4);
        float4 w1 = *(const float4*)(W_pos + HH + h4);
        float4 w2 = *(const float4*)(W_pos + 2*HH + h4);
        float4 bb = *(const float4*)(b_pos + h4);
        float4 ov;
        ov.x = fmaf(qz, w2.x, fmaf(qy, w1.x, fmaf(qx, w0.x, bb.x)));
        ov.y = fmaf(qz, w2.y, fmaf(qy, w1.y, fmaf(qx, w0.y, bb.y)));
        ov.z = fmaf(qz, w2.z, fmaf(qy, w1.z, fmaf(qx, w0.z, bb.z)));
        ov.w = fmaf(qz, w2.w, fmaf(qy, w1.w, fmaf(qx, w0.w, bb.w)));
        *(float4*)(dst + h4) = ov;
    }
}

// ======================= attention (gather + softmax) ===================
__global__ __launch_bounds__(256) void attn_kernel(const float* __restrict__ p,
                                                   const float* __restrict__ wc,
                                                   const float* __restrict__ bc)
{
    const int warp = threadIdx.x >> 5;
    const int lane = threadIdx.x & 31;
    const int t  = blockIdx.x * 8 + warp;
    const int b  = t >> 12;
    const int tt = t & (TT - 1);
    const float* pb = p + (size_t)b * TT * 3;

    const float q0 = pb[tt*3+0], q1 = pb[tt*3+1], q2 = pb[tt*3+2];
    const float w0 = wc[0], w1 = wc[1], w2 = wc[2], w3 = wc[3];
    const float w4 = wc[4], w5 = wc[5], w6 = wc[6], bcv = bc[0];

    float s = -FLT_MAX;
    int   j = 0;
    if (lane < KK) {
        size_t o = (size_t)t * KK + lane;
        j = g_idx[o];
        float d = g_dis[o];
        const float* px = pb + (size_t)j * 3;
        s = bcv;
        s = fmaf(w0, d,     s);
        s = fmaf(w1, px[0], s);
        s = fmaf(w2, px[1], s);
        s = fmaf(w3, px[2], s);
        s = fmaf(w4, q0,    s);
        s = fmaf(w5, q1,    s);
        s = fmaf(w6, q2,    s);
    }
    float m = s;
#pragma unroll
    for (int off = 16; off; off >>= 1)
        m = fmaxf(m, __shfl_xor_sync(0xffffffffu, m, off));
    float e = (lane < KK) ? expf(s - m) : 0.0f;
    float sum = e;
#pragma unroll
    for (int off = 16; off; off >>= 1)
        sum += __shfl_xor_sync(0xffffffffu, sum, off);
    const float inv = 1.0f / sum;

    float4 acc = make_float4(0.f, 0.f, 0.f, 0.f);
    const float* nb = g_net + (size_t)b * TT * HH;
#pragma unroll
    for (int k = 0; k < KK; ++k) {
        float wk = __shfl_sync(0xffffffffu, e, k) * inv;
        int   jk = __shfl_sync(0xffffffffu, j, k);
        float4 v = *(const float4*)(nb + (size_t)jk * HH + lane * 4);
        acc.x = fmaf(wk, v.x, acc.x);
        acc.y = fmaf(wk, v.y, acc.y);
        acc.z = fmaf(wk, v.z, acc.z);
        acc.w = fmaf(wk, v.w, acc.w);
    }
    *(float4*)(g_att + (size_t)t * HH + lane * 4) = acc;
}

// ======================= weight prep (quad-packed bf16) ==================
__global__ __launch_bounds__(256) void prep_weights(
    const float* __restrict__ Wo, const float* __restrict__ W0,
    const float* __restrict__ W1, const float* __restrict__ Ws)
{
    const int blk = blockIdx.y;
    const int slot = blockIdx.x;
    const float* W; int ck;
    if (slot < 8)       { W = Wo + (size_t)blk*128*128; ck = slot; }
    else if (slot < 24) { W = W0 + (size_t)blk*256*128; ck = slot-8; }
    else if (slot < 32) { W = W1 + (size_t)blk*128*128; ck = slot-24; }
    else                { W = Ws + (size_t)blk*256*128; ck = slot-32; }
    float* img = g_bprep + ((size_t)blk*48 + slot)*2048;

    for (int it = threadIdx.x; it < 512; it += 256) {
        int n = it >> 2, t = it & 3;
        int k0 = ck*16 + 2*t;
        float a0 = W[(size_t)k0*128 + n];
        float a1 = W[(size_t)(k0+1)*128 + n];
        float a2 = W[(size_t)(k0+8)*128 + n];
        float a3 = W[(size_t)(k0+9)*128 + n];
        uint32_t h0, l0, h1, l1;
        split2(a0, a1, h0, l0);
        split2(a2, a3, h1, l1);
        uint4 q = make_uint4(h0, h1, l0, l1);
        *(uint4*)(img + n*16 + t*4) = q;
    }
}

// ======================= tensor-core resnet (64-token CTA, 2 CTAs/SM) ====
__device__ __forceinline__ void init_acc(float acc[2][4][4],
                                         const float* __restrict__ bias,
                                         int nb, int tig)
{
#pragma unroll
    for (int j = 0; j < 4; ++j) {
        int col0 = nb + j*8 + 2*tig;
        float b0v = __ldg(bias + col0);
        float b1v = __ldg(bias + col0 + 1);
#pragma unroll
        for (int mt = 0; mt < 2; ++mt) {
            acc[mt][j][0] = b0v; acc[mt][j][1] = b1v;
            acc[mt][j][2] = b0v; acc[mt][j][3] = b1v;
        }
    }
}

// zero both hi/lo halves of the split where the hi half is negative
__device__ __forceinline__ void relu_mask(uint32_t& ah, uint32_t& al)
{
    uint32_t t = ah & 0x80008000u;
    uint32_t m = t - (t >> 15);
    uint32_t full = t | m;
    ah &= ~full;
    al &= ~full;
}

template<bool RELU>
__device__ __forceinline__ void gemm_tc(
    const uint32_t* At, const float* __restrict__ prep, int nchunks,
    float acc[2][4][4], uint32_t* Bs, int tid, int rb, int nb)
{
    const int lane = tid & 31;
    const int gid = lane >> 2, tig = lane & 3;

    // stage chunk 0
    __syncthreads();
    {
        const float4* s = (const float4*)prep;
        *(float4*)(Bs + tid*4)        = s[tid];
        *(float4*)(Bs + 1024 + tid*4) = s[tid + 256];
    }
    __syncthreads();

    for (int c = 0; c < nchunks; ++c) {
        const uint32_t* buf = Bs + (c & 1) * 2048;
        float4 pre0, pre1;
        if (c + 1 < nchunks) {
            const float4* s = (const float4*)(prep + (size_t)(c+1) * 2048);
            pre0 = s[tid];
            pre1 = s[tid + 256];
        }

        uint32_t Ah[2][4], Al[2][4];
#pragma unroll
        for (int mt = 0; mt < 2; ++mt) {
            const uint32_t* ap = At + (size_t)c*1024 + (rb + mt*16 + gid)*16 + tig*4;
            uint4 qa = *(const uint4*)ap;
            uint4 qb = *(const uint4*)(ap + 128);   // row + 8
            Ah[mt][0] = qa.x; Ah[mt][2] = qa.y; Al[mt][0] = qa.z; Al[mt][2] = qa.w;
            Ah[mt][1] = qb.x; Ah[mt][3] = qb.y; Al[mt][1] = qb.z; Al[mt][3] = qb.w;
            if (RELU) {
#pragma unroll
                for (int i = 0; i < 4; ++i)
                    relu_mask(Ah[mt][i], Al[mt][i]);
            }
        }
#pragma unroll
        for (int j = 0; j < 4; ++j) {
            const int n = nb + j*8 + gid;
            uint4 q = *(const uint4*)(buf + n*16 + tig*4);
            uint32_t bh[2] = { q.x, q.y };
            uint32_t bl[2] = { q.z, q.w };
#pragma unroll
            for (int mt = 0; mt < 2; ++mt) {
                MMA_BF16(acc[mt][j], Ah[mt], bh);
                MMA_BF16(acc[mt][j], Al[mt], bh);
                MMA_BF16(acc[mt][j], Ah[mt], bl);
            }
        }
        if (c + 1 < nchunks) {
            uint32_t* nbuf = Bs + ((c+1) & 1) * 2048;
            *(float4*)(nbuf + tid*4)        = pre0;
            *(float4*)(nbuf + 1024 + tid*4) = pre1;
        }
        __syncthreads();
    }
}

// store accumulators into a quad-packed bf16 tile (optionally relu'd first)
template<bool RELU>
__device__ __forceinline__ void store_acc_tile(float acc[2][4][4], uint32_t* tile,
                                               int rb, int nb, int lane)
{
    const int gid = lane >> 2, tig = lane & 3;
#pragma unroll
    for (int mt = 0; mt < 2; ++mt) {
        const int rg = rb + mt*16 + gid;
#pragma unroll
        for (int j = 0; j < 4; ++j) {
            const int kp = (nb >> 1) + j*4 + tig;     // global kpair 0..63
            const int c = kp >> 3, tq = kp & 7;
            const int base = c*1024 + (tq & 3)*4 + (tq >> 2);
            float v0 = acc[mt][j][0], v1 = acc[mt][j][1];
            float v2 = acc[mt][j][2], v3 = acc[mt][j][3];
            if (RELU) {
                v0 = fmaxf(v0, 0.f); v1 = fmaxf(v1, 0.f);
                v2 = fmaxf(v2, 0.f); v3 = fmaxf(v3, 0.f);
            }
            uint32_t wh, wl;
            split2(v0, v1, wh, wl);
            tile[base + rg*16]     = wh;
            tile[base + rg*16 + 2] = wl;
            split2(v2, v3, wh, wl);
            tile[base + (rg+8)*16]     = wh;
            tile[base + (rg+8)*16 + 2] = wl;
        }
    }
}

__global__ __launch_bounds__(256, 2) void resnet_tc(
    int blk,
    const float* __restrict__ b0, const float* __restrict__ b1,
    const float* __restrict__ bo, int add_res)
{
    extern __shared__ uint32_t sm[];
    uint32_t* xs  = sm;               // [ATILE]
    uint32_t* as_ = sm + ATILE;
    uint32_t* hs  = sm + 2*ATILE;
    uint32_t* Bs  = sm + 3*ATILE;     // 2 x 2048 double buffer

    const int tid = threadIdx.x;
    const int wid = tid >> 5, lane = tid & 31;
    const int rb = (wid & 1) * 32;          // 2 row groups of 32
    const int nb = (wid >> 1) * 32;         // 4 col groups of 32
    const int gid = lane >> 2, tig = lane & 3;
    const size_t t0 = (size_t)blockIdx.x * 64;
    const float* prep = g_bprep + (size_t)blk * 48 * 2048;

    // build xs (net) and hs (att) quad-packed images (64 rows)
    for (int it = tid; it < 2048; it += 256) {
        int r = it >> 5, rem = it & 31;
        int c = rem >> 2, t = rem & 3;
        int e0 = 16*c + 2*t;
        const float* src = g_net + (t0 + r) * HH;
        float2 p0 = *(const float2*)(src + e0);
        float2 p1 = *(const float2*)(src + e0 + 8);
        uint32_t h0, l0, h1, l1;
        split2(p0.x, p0.y, h0, l0);
        split2(p1.x, p1.y, h1, l1);
        *(uint4*)(xs + c*1024 + r*16 + t*4) = make_uint4(h0, h1, l0, l1);
        src = g_att + (t0 + r) * HH;
        p0 = *(const float2*)(src + e0);
        p1 = *(const float2*)(src + e0 + 8);
        split2(p0.x, p0.y, h0, l0);
        split2(p1.x, p1.y, h1, l1);
        *(uint4*)(hs + c*1024 + r*16 + t*4) = make_uint4(h0, h1, l0, l1);
    }

    float acc[2][4][4];

    // ---- GEMM1: a1 = att @ Wo^T + bo -> as_ (plain split)
    init_acc(acc, bo, nb, tig);
    gemm_tc<false>(hs, prep + 0*2048, 8, acc, Bs, tid, rb, nb);
    store_acc_tile<false>(acc, as_, rb, nb, lane);

    // ---- GEMM2: h = relu(relu([x|a1]) @ W0 + b0) -> hs (relu'd split)
    init_acc(acc, b0, nb, tig);
    gemm_tc<true>(xs,  prep + 8*2048,  8, acc, Bs, tid, rb, nb);
    gemm_tc<true>(as_, prep + 16*2048, 8, acc, Bs, tid, rb, nb);
    __syncthreads();
    store_acc_tile<true>(acc, hs, rb, nb, lane);

    // ---- GEMM3+4: out = h @ W1^T + b1 + [x|a1] @ Ws^T [+ residual]
    init_acc(acc, b1, nb, tig);
    gemm_tc<false>(hs,  prep + 24*2048, 8, acc, Bs, tid, rb, nb);
    gemm_tc<false>(xs,  prep + 32*2048, 8, acc, Bs, tid, rb, nb);
    gemm_tc<false>(as_, prep + 40*2048, 8, acc, Bs, tid, rb, nb);

#pragma unroll
    for (int mt = 0; mt < 2; ++mt) {
        const int rg = rb + mt*16 + gid;
#pragma unroll
        for (int j = 0; j < 4; ++j) {
            const int col0 = nb + j*8 + 2*tig;
            float v0 = acc[mt][j][0], v1 = acc[mt][j][1];
            float v2 = acc[mt][j][2], v3 = acc[mt][j][3];
            float* d0 = g_net + (t0 + rg) * HH + col0;
            float* d1 = g_net + (t0 + rg + 8) * HH + col0;
            if (add_res) {
                float2 r0 = *(const float2*)d0;
                float2 r1 = *(const float2*)d1;
                v0 += r0.x; v1 += r0.y; v2 += r1.x; v3 += r1.y;
            }
            *(float2*)d0 = make_float2(v0, v1);
            *(float2*)d1 = make_float2(v2, v3);
        }
    }
}

// ======================= final projection (scalar, FFMA2) ===============
__device__ __forceinline__ void init_bias_f(u64 acc[8][4], const float* __restrict__ bias, int nb)
{
    ulonglong2 q0 = *(const ulonglong2*)(bias + nb);
    ulonglong2 q1 = *(const ulonglong2*)(bias + nb + 4);
#pragma unroll
    for (int r = 0; r < 8; ++r) {
        acc[r][0] = q0.x; acc[r][1] = q0.y; acc[r][2] = q1.x; acc[r][3] = q1.y;
    }
}

__global__ __launch_bounds__(256) void final_kernel(const float* __restrict__ W_c,
                                                    const float* __restrict__ b_c,
                                                    float* __restrict__ out)
{
    extern __shared__ float smf[];
    float* xs = smf;             // [128][SX]
    float* ws = smf + 128 * SX;  // [32][128]

    const int tid = threadIdx.x;
    const int tx = tid & 15;
    const int ty = tid >> 4;
    const int nb = tx * 8;
    const int rb = ty * 8;
    const size_t t0 = (size_t)blockIdx.x * 128;

    for (int q = tid; q < 128 * 32; q += 256) {
        int r = q >> 5, c = (q & 31) << 2;
        *(float4*)(xs + r * SX + c) = *(const float4*)(g_net + (t0 + r) * HH + c);
    }

    u64 acc[8][4];
    init_bias_f(acc, b_c, nb);

    for (int kt = 0; kt < 128; kt += 32) {
        __syncthreads();
        for (int q = tid; q < 1024; q += 256) {
            int kk = q >> 5, c = (q & 31) << 2;
            *(float4*)(ws + kk * 128 + c) = *(const float4*)(W_c + (size_t)(kt + kk) * 128 + c);
        }
        __syncthreads();
#pragma unroll 1
        for (int k4 = 0; k4 < 8; ++k4) {
            float4 a4[8];
#pragma unroll
            for (int r = 0; r < 8; ++r)
                a4[r] = *(const float4*)(xs + (rb + r) * SX + kt + k4 * 4);
#pragma unroll
            for (int j = 0; j < 4; ++j) {
                int kk = k4 * 4 + j;
                ulonglong2 b0v = *(const ulonglong2*)(ws + kk * 128 + nb);
                ulonglong2 b1v = *(const ulonglong2*)(ws + kk * 128 + nb + 4);
#pragma unroll
                for (int r = 0; r < 8; ++r) {
                    float a = ((const float*)&a4[r])[j];
                    u64 aa; BCAST2(aa, __float_as_uint(a));
                    FMA2(acc[r][0], aa, b0v.x, acc[r][0]);
                    FMA2(acc[r][1], aa, b0v.y, acc[r][1]);
                    FMA2(acc[r][2], aa, b1v.x, acc[r][2]);
                    FMA2(acc[r][3], aa, b1v.y, acc[r][3]);
                }
            }
        }
    }
#pragma unroll
    for (int r = 0; r < 8; ++r) {
        *(ulonglong2*)(out + (t0 + rb + r) * HH + nb)     = make_ulonglong2(acc[r][0], acc[r][1]);
        *(ulonglong2*)(out + (t0 + rb + r) * HH + nb + 4) = make_ulonglong2(acc[r][2], acc[r][3]);
    }
}

// ======================= launch =========================================
extern "C" void kernel_launch(void* const* d_in, const int* in_sizes, int n_in,
                              void* d_out, int out_size)
{
    const float* p      = (const float*)d_in[0];
    const float* W_pos  = (const float*)d_in[1];
    const float* b_pos  = (const float*)d_in[2];
    const float* blk_W0 = (const float*)d_in[3];
    const float* blk_b0 = (const float*)d_in[4];
    const float* blk_W1 = (const float*)d_in[5];
    const float* blk_b1 = (const float*)d_in[6];
    const float* blk_Ws = (const float*)d_in[7];
    const float* att_Wc = (const float*)d_in[8];
    const float* att_bc = (const float*)d_in[9];
    const float* att_Wo = (const float*)d_in[10];
    const float* att_bo = (const float*)d_in[11];
    const float* W_c    = (const float*)d_in[12];
    const float* b_c    = (const float*)d_in[13];
    float* out = (float*)d_out;

    const int RES_SMEM = (3 * ATILE + 2 * 2048) * 4;   // 114,688 B -> 2 CTAs/SM
    const int FIN_SMEM = (128 * SX + 32 * 128) * 4;    //  83,968 B
    cudaFuncSetAttribute(resnet_tc,   cudaFuncAttributeMaxDynamicSharedMemorySize, RES_SMEM);
    cudaFuncSetAttribute(final_kernel, cudaFuncAttributeMaxDynamicSharedMemorySize, FIN_SMEM);

    // launch order: raw2=prep, raw3=knn(+pos), raw4=attn0, raw5=resnet0
    prep_weights<<<dim3(48, NBLK), 256>>>(att_Wo, blk_W0, blk_W1, blk_Ws);
    knn_kernel<<<dim3(TT / 128, BB), 128>>>(p, W_pos, b_pos);

    for (int i = 0; i < NBLK; ++i) {
        attn_kernel<<<BT / 8, 256>>>(p, att_Wc + (size_t)i * 7, att_bc + i);
        resnet_tc<<<BT / 64, 256, RES_SMEM>>>(
            i, blk_b0 + (size_t)i * 128, blk_b1 + (size_t)i * 128,
            att_bo + (size_t)i * 128, i > 0 ? 1 : 0);
    }
    final_kernel<<<BT / 128, 256, FIN_SMEM>>>(W_c, b_c, out);
}

// round 17
// speedup vs baseline: 1.0752x; 1.0001x over previous
#include <cuda_runtime.h>
#include <cuda_bf16.h>
#include <math.h>
#include <float.h>
#include <stdint.h>

#define BB 8
#define TT 4096
#define HH 128
#define NBLK 6
#define KK 20
#define BT (BB*TT)   // 32768
#define SX 132       // f32 tile stride (final_kernel only)
#define ATILE 8192   // A image words per tile: 8 chunks x 64 rows x 16 words

typedef unsigned long long u64;

// packed f32x2 helpers (scalar kernels)
#define FMA2(d, a, b, c) \
    asm("fma.rn.f32x2 %0, %1, %2, %3;" : "=l"(d) : "l"(a), "l"(b), "l"(c))
#define BCAST2(d, s) \
    asm("mov.b64 %0, {%1, %1};" : "=l"(d) : "r"(s))

// bf16 mma (sm_80+ PTX, valid at target sm_103)
#define MMA_BF16(d, a, b) \
    asm volatile("mma.sync.aligned.m16n8k16.row.col.f32.bf16.bf16.f32 " \
        "{%0,%1,%2,%3}, {%4,%5,%6,%7}, {%8,%9}, {%0,%1,%2,%3};" \
        : "+f"((d)[0]), "+f"((d)[1]), "+f"((d)[2]), "+f"((d)[3]) \
        : "r"((a)[0]), "r"((a)[1]), "r"((a)[2]), "r"((a)[3]), \
          "r"((b)[0]), "r"((b)[1]))

// pack two f32 into bf16x2: low 16 bits <- vlo, high <- vhi
__device__ __forceinline__ uint32_t pack_bf16x2(float vlo, float vhi) {
    uint32_t r;
    asm("cvt.rn.bf16x2.f32 %0, %1, %2;" : "=r"(r) : "f"(vhi), "f"(vlo));
    return r;
}

// split f32 pair -> (hi word, lo word)
__device__ __forceinline__ void split2(float x, float y, uint32_t& wh, uint32_t& wl) {
    wh = pack_bf16x2(x, y);
    float h0 = __uint_as_float(wh << 16);
    float h1 = __uint_as_float(wh & 0xffff0000u);
    wl = pack_bf16x2(x - h0, y - h1);
}

// ---------------- scratch (device globals; no allocation) ----------------
__device__ float g_net[BT * HH];   // 16 MB
__device__ float g_att[BT * HH];   // 16 MB
__device__ int   g_idx[BT * KK];
__device__ float g_dis[BT * KK];
// prepped weights: per block 48 K16-chunks x 2048 quad-packed words
__device__ float g_bprep[NBLK * 48 * 2048];   // 2.4 MB

// ======================= KNN (smem top-20, replace-max) =================
// 128 threads/block, 1 query/thread. Top-20 kept UNSORTED in shared memory
// (per-thread column, conflict-free); register-cached (max, argmax) makes
// the threshold test cheap and the insert path ~85 slots instead of ~140.
// Output order is arbitrary (softmax over K is permutation-invariant).
__global__ __launch_bounds__(128) void knn_kernel(const float* __restrict__ p,
                                                  const float* __restrict__ W_pos,
                                                  const float* __restrict__ b_pos)
{
    __shared__ float4 sp[1024];       // candidate window tile
    __shared__ float  sd[KK * 128];   // distances, sd[k*128+tid]
    __shared__ int    si[KK * 128];   // indices

    const int b   = blockIdx.y;
    const int tid = threadIdx.x;
    const int tt  = blockIdx.x * 128 + tid;
    const float* pb = p + (size_t)b * TT * 3;

    const float qx = pb[tt*3 + 0];
    const float qy = pb[tt*3 + 1];
    const float qz = pb[tt*3 + 2];
    const float sqq = (qx*qx + qy*qy) + qz*qz;

#pragma unroll
    for (int k = 0; k < KK; ++k) sd[k*128 + tid] = FLT_MAX;
    float maxv = FLT_MAX;
    int   maxslot = 0;

    for (int s0 = 0; s0 < TT; s0 += 1024) {
        __syncthreads();
        for (int l = tid; l < 1024; l += 128) {
            const float* q = pb + (size_t)(s0 + l) * 3;
            float x = q[0], y = q[1], z = q[2];
            sp[l] = make_float4(x, y, z, (x*x + y*y) + z*z);
        }
        __syncthreads();
#pragma unroll 4
        for (int l = 0; l < 1024; ++l) {
            float4 v = sp[l];
            float dot = qx*v.x + qy*v.y + qz*v.z;
            float d2  = sqq + v.w - 2.0f * dot;
            if (d2 < maxv) {
                sd[maxslot*128 + tid] = d2;
                si[maxslot*128 + tid] = s0 + l;
                float mv = sd[tid];
                int   m  = 0;
#pragma unroll
                for (int k = 1; k < KK; ++k) {
                    float w = sd[k*128 + tid];
                    if (w > mv) { mv = w; m = k; }
                }
                maxv = mv;
                maxslot = m;
            }
        }
    }

    const size_t o = ((size_t)b * TT + tt) * KK;
#pragma unroll
    for (int k = 0; k < KK; ++k) {
        g_idx[o + k] = si[k*128 + tid];
        g_dis[o + k] = sqrtf(fmaxf(sd[k*128 + tid], 1e-12f));
    }

    // ---- fused positional encoding
    float* dst = g_net + ((size_t)b * TT + tt) * HH;
#pragma unroll 4
    for (int h4 = 0; h4 < HH; h4 += 4) {
        float4 w0 = *(const float4*)(W_pos + h4);
        float4 w1 = *(const float4*)(W_pos + HH + h4);
        float4 w2 = *(const float4*)(W_pos + 2*HH + h4);
        float4 bb = *(const float4*)(b_pos + h4);
        float4 ov;
        ov.x = fmaf(qz, w2.x, fmaf(qy, w1.x, fmaf(qx, w0.x, bb.x)));
        ov.y = fmaf(qz, w2.y, fmaf(qy, w1.y, fmaf(qx, w0.y, bb.y)));
        ov.z = fmaf(qz, w2.z, fmaf(qy, w1.z, fmaf(qx, w0.z, bb.z)));
        ov.w = fmaf(qz, w2.w, fmaf(qy, w1.w, fmaf(qx, w0.w, bb.w)));
        *(float4*)(dst + h4) = ov;
    }
}

// ======================= attention (gather + softmax) ===================
__global__ __launch_bounds__(256) void attn_kernel(const float* __restrict__ p,
                                                   const float* __restrict__ wc,
                                                   const float* __restrict__ bc)
{
    const int warp = threadIdx.x >> 5;
    const int lane = threadIdx.x & 31;
    const int t  = blockIdx.x * 8 + warp;
    const int b  = t >> 12;
    const int tt = t & (TT - 1);
    const float* pb = p + (size_t)b * TT * 3;

    const float q0 = pb[tt*3+0], q1 = pb[tt*3+1], q2 = pb[tt*3+2];
    const float w0 = wc[0], w1 = wc[1], w2 = wc[2], w3 = wc[3];
    const float w4 = wc[4], w5 = wc[5], w6 = wc[6], bcv = bc[0];

    float s = -FLT_MAX;
    int   j = 0;
    if (lane < KK) {
        size_t o = (size_t)t * KK + lane;
        j = g_idx[o];
        float d = g_dis[o];
        const float* px = pb + (size_t)j * 3;
        s = bcv;
        s = fmaf(w0, d,     s);
        s = fmaf(w1, px[0], s);
        s = fmaf(w2, px[1], s);
        s = fmaf(w3, px[2], s);
        s = fmaf(w4, q0,    s);
        s = fmaf(w5, q1,    s);
        s = fmaf(w6, q2,    s);
    }
    float m = s;
#pragma unroll
    for (int off = 16; off; off >>= 1)
        m = fmaxf(m, __shfl_xor_sync(0xffffffffu, m, off));
    float e = (lane < KK) ? expf(s - m) : 0.0f;
    float sum = e;
#pragma unroll
    for (int off = 16; off; off >>= 1)
        sum += __shfl_xor_sync(0xffffffffu, sum, off);
    const float inv = 1.0f / sum;

    float4 acc = make_float4(0.f, 0.f, 0.f, 0.f);
    const float* nb = g_net + (size_t)b * TT * HH;
#pragma unroll
    for (int k = 0; k < KK; ++k) {
        float wk = __shfl_sync(0xffffffffu, e, k) * inv;
        int   jk = __shfl_sync(0xffffffffu, j, k);
        float4 v = *(const float4*)(nb + (size_t)jk * HH + lane * 4);
        acc.x = fmaf(wk, v.x, acc.x);
        acc.y = fmaf(wk, v.y, acc.y);
        acc.z = fmaf(wk, v.z, acc.z);
        acc.w = fmaf(wk, v.w, acc.w);
    }
    *(float4*)(g_att + (size_t)t * HH + lane * 4) = acc;
}

// ======================= weight prep (quad-packed bf16) ==================
__global__ __launch_bounds__(256) void prep_weights(
    const float* __restrict__ Wo, const float* __restrict__ W0,
    const float* __restrict__ W1, const float* __restrict__ Ws)
{
    const int blk = blockIdx.y;
    const int slot = blockIdx.x;
    const float* W; int ck;
    if (slot < 8)       { W = Wo + (size_t)blk*128*128; ck = slot; }
    else if (slot < 24) { W = W0 + (size_t)blk*256*128; ck = slot-8; }
    else if (slot < 32) { W = W1 + (size_t)blk*128*128; ck = slot-24; }
    else                { W = Ws + (size_t)blk*256*128; ck = slot-32; }
    float* img = g_bprep + ((size_t)blk*48 + slot)*2048;

    for (int it = threadIdx.x; it < 512; it += 256) {
        int n = it >> 2, t = it & 3;
        int k0 = ck*16 + 2*t;
        float a0 = W[(size_t)k0*128 + n];
        float a1 = W[(size_t)(k0+1)*128 + n];
        float a2 = W[(size_t)(k0+8)*128 + n];
        float a3 = W[(size_t)(k0+9)*128 + n];
        uint32_t h0, l0, h1, l1;
        split2(a0, a1, h0, l0);
        split2(a2, a3, h1, l1);
        uint4 q = make_uint4(h0, h1, l0, l1);
        *(uint4*)(img + n*16 + t*4) = q;
    }
}

// ======================= tensor-core resnet (64-token CTA, 2 CTAs/SM) ====
__device__ __forceinline__ void init_acc(float acc[2][4][4],
                                         const float* __restrict__ bias,
                                         int nb, int tig)
{
#pragma unroll
    for (int j = 0; j < 4; ++j) {
        int col0 = nb + j*8 + 2*tig;
        float b0v = __ldg(bias + col0);
        float b1v = __ldg(bias + col0 + 1);
#pragma unroll
        for (int mt = 0; mt < 2; ++mt) {
            acc[mt][j][0] = b0v; acc[mt][j][1] = b1v;
            acc[mt][j][2] = b0v; acc[mt][j][3] = b1v;
        }
    }
}

// zero both hi/lo halves of the split where the hi half is negative
__device__ __forceinline__ void relu_mask(uint32_t& ah, uint32_t& al)
{
    uint32_t t = ah & 0x80008000u;
    uint32_t m = t - (t >> 15);
    uint32_t full = t | m;
    ah &= ~full;
    al &= ~full;
}

template<bool RELU>
__device__ __forceinline__ void gemm_tc(
    const uint32_t* At, const float* __restrict__ prep, int nchunks,
    float acc[2][4][4], uint32_t* Bs, int tid, int rb, int nb)
{
    const int lane = tid & 31;
    const int gid = lane >> 2, tig = lane & 3;

    // stage chunk 0
    __syncthreads();
    {
        const float4* s = (const float4*)prep;
        *(float4*)(Bs + tid*4)        = s[tid];
        *(float4*)(Bs + 1024 + tid*4) = s[tid + 256];
    }
    __syncthreads();

    for (int c = 0; c < nchunks; ++c) {
        const uint32_t* buf = Bs + (c & 1) * 2048;
        float4 pre0, pre1;
        if (c + 1 < nchunks) {
            const float4* s = (const float4*)(prep + (size_t)(c+1) * 2048);
            pre0 = s[tid];
            pre1 = s[tid + 256];
        }

        uint32_t Ah[2][4], Al[2][4];
#pragma unroll
        for (int mt = 0; mt < 2; ++mt) {
            const uint32_t* ap = At + (size_t)c*1024 + (rb + mt*16 + gid)*16 + tig*4;
            uint4 qa = *(const uint4*)ap;
            uint4 qb = *(const uint4*)(ap + 128);   // row + 8
            Ah[mt][0] = qa.x; Ah[mt][2] = qa.y; Al[mt][0] = qa.z; Al[mt][2] = qa.w;
            Ah[mt][1] = qb.x; Ah[mt][3] = qb.y; Al[mt][1] = qb.z; Al[mt][3] = qb.w;
            if (RELU) {
#pragma unroll
                for (int i = 0; i < 4; ++i)
                    relu_mask(Ah[mt][i], Al[mt][i]);
            }
        }
#pragma unroll
        for (int j = 0; j < 4; ++j) {
            const int n = nb + j*8 + gid;
            uint4 q = *(const uint4*)(buf + n*16 + tig*4);
            uint32_t bh[2] = { q.x, q.y };
            uint32_t bl[2] = { q.z, q.w };
#pragma unroll
            for (int mt = 0; mt < 2; ++mt) {
                MMA_BF16(acc[mt][j], Ah[mt], bh);
                MMA_BF16(acc[mt][j], Al[mt], bh);
                MMA_BF16(acc[mt][j], Ah[mt], bl);
            }
        }
        if (c + 1 < nchunks) {
            uint32_t* nbuf = Bs + ((c+1) & 1) * 2048;
            *(float4*)(nbuf + tid*4)        = pre0;
            *(float4*)(nbuf + 1024 + tid*4) = pre1;
        }
        __syncthreads();
    }
}

// store accumulators into a quad-packed bf16 tile (optionally relu'd first)
template<bool RELU>
__device__ __forceinline__ void store_acc_tile(float acc[2][4][4], uint32_t* tile,
                                               int rb, int nb, int lane)
{
    const int gid = lane >> 2, tig = lane & 3;
#pragma unroll
    for (int mt = 0; mt < 2; ++mt) {
        const int rg = rb + mt*16 + gid;
#pragma unroll
        for (int j = 0; j < 4; ++j) {
            const int kp = (nb >> 1) + j*4 + tig;     // global kpair 0..63
            const int c = kp >> 3, tq = kp & 7;
            const int base = c*1024 + (tq & 3)*4 + (tq >> 2);
            float v0 = acc[mt][j][0], v1 = acc[mt][j][1];
            float v2 = acc[mt][j][2], v3 = acc[mt][j][3];
            if (RELU) {
                v0 = fmaxf(v0, 0.f); v1 = fmaxf(v1, 0.f);
                v2 = fmaxf(v2, 0.f); v3 = fmaxf(v3, 0.f);
            }
            uint32_t wh, wl;
            split2(v0, v1, wh, wl);
            tile[base + rg*16]     = wh;
            tile[base + rg*16 + 2] = wl;
            split2(v2, v3, wh, wl);
            tile[base + (rg+8)*16]     = wh;
            tile[base + (rg+8)*16 + 2] = wl;
        }
    }
}

__global__ __launch_bounds__(256, 2) void resnet_tc(
    int blk,
    const float* __restrict__ b0, const float* __restrict__ b1,
    const float* __restrict__ bo, int add_res)
{
    extern __shared__ uint32_t sm[];
    uint32_t* xs  = sm;               // [ATILE]
    uint32_t* as_ = sm + ATILE;
    uint32_t* hs  = sm + 2*ATILE;
    uint32_t* Bs  = sm + 3*ATILE;     // 2 x 2048 double buffer

    const int tid = threadIdx.x;
    const int wid = tid >> 5, lane = tid & 31;
    const int rb = (wid & 1) * 32;          // 2 row groups of 32
    const int nb = (wid >> 1) * 32;         // 4 col groups of 32
    const int gid = lane >> 2, tig = lane & 3;
    const size_t t0 = (size_t)blockIdx.x * 64;
    const float* prep = g_bprep + (size_t)blk * 48 * 2048;

    // build xs (net) and hs (att) quad-packed images (64 rows)
    for (int it = tid; it < 2048; it += 256) {
        int r = it >> 5, rem = it & 31;
        int c = rem >> 2, t = rem & 3;
        int e0 = 16*c + 2*t;
        const float* src = g_net + (t0 + r) * HH;
        float2 p0 = *(const float2*)(src + e0);
        float2 p1 = *(const float2*)(src + e0 + 8);
        uint32_t h0, l0, h1, l1;
        split2(p0.x, p0.y, h0, l0);
        split2(p1.x, p1.y, h1, l1);
        *(uint4*)(xs + c*1024 + r*16 + t*4) = make_uint4(h0, h1, l0, l1);
        src = g_att + (t0 + r) * HH;
        p0 = *(const float2*)(src + e0);
        p1 = *(const float2*)(src + e0 + 8);
        split2(p0.x, p0.y, h0, l0);
        split2(p1.x, p1.y, h1, l1);
        *(uint4*)(hs + c*1024 + r*16 + t*4) = make_uint4(h0, h1, l0, l1);
    }

    float acc[2][4][4];

    // ---- GEMM1: a1 = att @ Wo^T + bo -> as_ (plain split)
    init_acc(acc, bo, nb, tig);
    gemm_tc<false>(hs, prep + 0*2048, 8, acc, Bs, tid, rb, nb);
    store_acc_tile<false>(acc, as_, rb, nb, lane);

    // ---- GEMM2: h = relu(relu([x|a1]) @ W0 + b0) -> hs (relu'd split)
    init_acc(acc, b0, nb, tig);
    gemm_tc<true>(xs,  prep + 8*2048,  8, acc, Bs, tid, rb, nb);
    gemm_tc<true>(as_, prep + 16*2048, 8, acc, Bs, tid, rb, nb);
    __syncthreads();
    store_acc_tile<true>(acc, hs, rb, nb, lane);

    // ---- GEMM3+4: out = h @ W1^T + b1 + [x|a1] @ Ws^T [+ residual]
    init_acc(acc, b1, nb, tig);
    gemm_tc<false>(hs,  prep + 24*2048, 8, acc, Bs, tid, rb, nb);
    gemm_tc<false>(xs,  prep + 32*2048, 8, acc, Bs, tid, rb, nb);
    gemm_tc<false>(as_, prep + 40*2048, 8, acc, Bs, tid, rb, nb);

#pragma unroll
    for (int mt = 0; mt < 2; ++mt) {
        const int rg = rb + mt*16 + gid;
#pragma unroll
        for (int j = 0; j < 4; ++j) {
            const int col0 = nb + j*8 + 2*tig;
            float v0 = acc[mt][j][0], v1 = acc[mt][j][1];
            float v2 = acc[mt][j][2], v3 = acc[mt][j][3];
            float* d0 = g_net + (t0 + rg) * HH + col0;
            float* d1 = g_net + (t0 + rg + 8) * HH + col0;
            if (add_res) {
                float2 r0 = *(const float2*)d0;
                float2 r1 = *(const float2*)d1;
                v0 += r0.x; v1 += r0.y; v2 += r1.x; v3 += r1.y;
            }
            *(float2*)d0 = make_float2(v0, v1);
            *(float2*)d1 = make_float2(v2, v3);
        }
    }
}

// ======================= final projection (scalar, FFMA2) ===============
__device__ __forceinline__ void init_bias_f(u64 acc[8][4], const float* __restrict__ bias, int nb)
{
    ulonglong2 q0 = *(const ulonglong2*)(bias + nb);
    ulonglong2 q1 = *(const ulonglong2*)(bias + nb + 4);
#pragma unroll
    for (int r = 0; r < 8; ++r) {
        acc[r][0] = q0.x; acc[r][1] = q0.y; acc[r][2] = q1.x; acc[r][3] = q1.y;
    }
}

__global__ __launch_bounds__(256) void final_kernel(const float* __restrict__ W_c,
                                                    const float* __restrict__ b_c,
                                                    float* __restrict__ out)
{
    extern __shared__ float smf[];
    float* xs = smf;             // [128][SX]
    float* ws = smf + 128 * SX;  // [32][128]

    const int tid = threadIdx.x;
    const int tx = tid & 15;
    const int ty = tid >> 4;
    const int nb = tx * 8;
    const int rb = ty * 8;
    const size_t t0 = (size_t)blockIdx.x * 128;

    for (int q = tid; q < 128 * 32; q += 256) {
        int r = q >> 5, c = (q & 31) << 2;
        *(float4*)(xs + r * SX + c) = *(const float4*)(g_net + (t0 + r) * HH + c);
    }

    u64 acc[8][4];
    init_bias_f(acc, b_c, nb);

    for (int kt = 0; kt < 128; kt += 32) {
        __syncthreads();
        for (int q = tid; q < 1024; q += 256) {
            int kk = q >> 5, c = (q & 31) << 2;
            *(float4*)(ws + kk * 128 + c) = *(const float4*)(W_c + (size_t)(kt + kk) * 128 + c);
        }
        __syncthreads();
#pragma unroll 1
        for (int k4 = 0; k4 < 8; ++k4) {
            float4 a4[8];
#pragma unroll
            for (int r = 0; r < 8; ++r)
                a4[r] = *(const float4*)(xs + (rb + r) * SX + kt + k4 * 4);
#pragma unroll
            for (int j = 0; j < 4; ++j) {
                int kk = k4 * 4 + j;
                ulonglong2 b0v = *(const ulonglong2*)(ws + kk * 128 + nb);
                ulonglong2 b1v = *(const ulonglong2*)(ws + kk * 128 + nb + 4);
#pragma unroll
                for (int r = 0; r < 8; ++r) {
                    float a = ((const float*)&a4[r])[j];
                    u64 aa; BCAST2(aa, __float_as_uint(a));
                    FMA2(acc[r][0], aa, b0v.x, acc[r][0]);
                    FMA2(acc[r][1], aa, b0v.y, acc[r][1]);
                    FMA2(acc[r][2], aa, b1v.x, acc[r][2]);
                    FMA2(acc[r][3], aa, b1v.y, acc[r][3]);
                }
            }
        }
    }
#pragma unroll
    for (int r = 0; r < 8; ++r) {
        *(ulonglong2*)(out + (t0 + rb + r) * HH + nb)     = make_ulonglong2(acc[r][0], acc[r][1]);
        *(ulonglong2*)(out + (t0 + rb + r) * HH + nb + 4) = make_ulonglong2(acc[r][2], acc[r][3]);
    }
}

// ======================= launch =========================================
extern "C" void kernel_launch(void* const* d_in, const int* in_sizes, int n_in,
                              void* d_out, int out_size)
{
    const float* p      = (const float*)d_in[0];
    const float* W_pos  = (const float*)d_in[1];
    const float* b_pos  = (const float*)d_in[2];
    const float* blk_W0 = (const float*)d_in[3];
    const float* blk_b0 = (const float*)d_in[4];
    const float* blk_W1 = (const float*)d_in[5];
    const float* blk_b1 = (const float*)d_in[6];
    const float* blk_Ws = (const float*)d_in[7];
    const float* att_Wc = (const float*)d_in[8];
    const float* att_bc = (const float*)d_in[9];
    const float* att_Wo = (const float*)d_in[10];
    const float* att_bo = (const float*)d_in[11];
    const float* W_c    = (const float*)d_in[12];
    const float* b_c    = (const float*)d_in[13];
    float* out = (float*)d_out;

    const int RES_SMEM = (3 * ATILE + 2 * 2048) * 4;   // 114,688 B -> 2 CTAs/SM
    const int FIN_SMEM = (128 * SX + 32 * 128) * 4;    //  83,968 B
    cudaFuncSetAttribute(resnet_tc,   cudaFuncAttributeMaxDynamicSharedMemorySize, RES_SMEM);
    cudaFuncSetAttribute(final_kernel, cudaFuncAttributeMaxDynamicSharedMemorySize, FIN_SMEM);

    // launch order: raw2=prep, raw3=knn(+pos), raw4=attn0, raw5=resnet0
    prep_weights<<<dim3(48, NBLK), 256>>>(att_Wo, blk_W0, blk_W1, blk_Ws);
    knn_kernel<<<dim3(TT / 128, BB), 128>>>(p, W_pos, b_pos);

    for (int i = 0; i < NBLK; ++i) {
        attn_kernel<<<BT / 8, 256>>>(p, att_Wc + (size_t)i * 7, att_bc + i);
        resnet_tc<<<BT / 64, 256, RES_SMEM>>>(
            i, blk_b0 + (size_t)i * 128, blk_b1 + (size_t)i * 128,
            att_bo + (size_t)i * 128, i > 0 ? 1 : 0);
    }
    final_kernel<<<BT / 128, 256, FIN_SMEM>>>(W_c, b_c, out);
}